// round 3
// baseline (speedup 1.0000x reference)
#include <cuda_runtime.h>
#include <cuda_bf16.h>

// ---------------------------------------------------------------------------
// SRF layer: grouped conv, filters = Gaussian-Hermite (order 2) bases mixed by
// learned alphas. 5 groups, 4 in-ch -> 8 out-ch per group. Separable basis.
//   precompute: sigma -> taps (lane-duplicated f32x2) + duplicated alphas.
//   conv: one combined kernel, runtime tap-count dispatch (3 vs 5) per group.
//     per-thread column pair: horizontal conv -> per-o-pair mixing (v2.u64
//     alpha loads) -> vertical scatter into T-deep accumulator ring, packed
//     f32x2 throughout. Head rows guard scatter (k<=i) against ghost terms.
// ---------------------------------------------------------------------------

#define H 384
#define W 384
#define B 16
#define INC 20
#define OUTC 40
#define NG 5
#define ICG 4
#define OCG 8
#define NB 6
#define SH 64          // strip height (384/64 = 6 strips)

__device__ float2 g_dp[NG][3][5];
__device__ float2 g_alpha[NG][NB][ICG][OCG];

typedef unsigned long long ull;

__device__ __forceinline__ ull pk2(float a, float b) {
    ull r; asm("mov.b64 %0, {%1, %2};" : "=l"(r) : "f"(a), "f"(b)); return r;
}
__device__ __forceinline__ ull fma2(ull a, ull b, ull c) {
    ull d; asm("fma.rn.f32x2 %0, %1, %2, %3;" : "=l"(d) : "l"(a), "l"(b), "l"(c));
    return d;
}
__device__ __forceinline__ void unpk2(ull v, float& lo, float& hi) {
    asm("mov.b64 {%0, %1}, %2;" : "=f"(lo), "=f"(hi) : "l"(v));
}

// ---- precompute ------------------------------------------------------------
__global__ void srf_precompute(const float* __restrict__ alphas,
                               const float* __restrict__ scales) {
    int tid = threadIdx.x;
    if (tid < NG) {
        const int FSarr[5] = {1, 1, 1, 2, 2};
        int s = tid;
        float mn = 0.2f * s, mx = mn + 0.2f;
        float sigma = (mx - mn) * 0.5f * tanhf(scales[s]) + (mn + mx) * 0.5f;
        int F = FSarr[s];
        int T = 2 * F + 1;
        float g[5];
        float sum = 0.f;
        for (int k = 0; k < T; ++k) {
            float x = (float)(k - F);
            g[k] = expf(-(x * x) / (2.f * sigma * sigma));
            sum += g[k];
        }
        float inv = 1.f / sum;
        float c1 = -1.f / (sigma * 1.41421356237309515f);
        for (int k = 0; k < 5; ++k) {
            float d0 = 0.f, d1 = 0.f, d2 = 0.f;
            if (k < T) {
                float x = (float)(k - F);
                float gg = g[k] * inv;
                float u = x / (sigma * 1.41421356237309515f);
                d0 = gg;
                d1 = c1 * (2.f * u) * gg;
                d2 = (c1 * c1) * (4.f * u * u - 2.f) * gg;
            }
            g_dp[s][0][k] = make_float2(d0, d0);
            g_dp[s][1][k] = make_float2(d1, d1);
            g_dp[s][2][k] = make_float2(d2, d2);
        }
    }
    for (int idx = tid; idx < NG * NB * ICG * OCG; idx += blockDim.x) {
        float a = alphas[idx];
        ((float2*)g_alpha)[idx] = make_float2(a, a);
    }
}

// ---- one row step ----------------------------------------------------------
template <int T, bool HEAD>
__device__ __forceinline__ void srf_row_step(
    int i, int u, int y0, int x0,
    const bool (&xv)[T + 1],
    const float* __restrict__ inb, float* __restrict__ outb,
    const ull (&dp)[3][T],
    const float2 (*__restrict__ sA)[ICG][OCG],
    ull (&acc)[T][OCG]) {
    constexpr int F = T / 2;
    const int IV[NB] = {0, 0, 0, 1, 1, 2};
    const int JH[NB] = {0, 1, 2, 0, 1, 0};

    int r = y0 - F + i;
    bool rv = (r >= 0 && r < H);

    // horizontal pass
    ull hh[ICG][3];
#pragma unroll
    for (int ch = 0; ch < ICG; ++ch) {
        const float* row = inb + ((size_t)ch * H + (size_t)(rv ? r : 0)) * W;
        float w[T + 1];
#pragma unroll
        for (int j = 0; j <= T; ++j) {
            int xx = x0 - F + j;
            w[j] = (rv && xv[j]) ? __ldg(row + xx) : 0.f;
        }
        ull pkv[T];
#pragma unroll
        for (int k = 0; k < T; ++k) pkv[k] = pk2(w[k], w[k + 1]);
#pragma unroll
        for (int jh = 0; jh < 3; ++jh) {
            ull a = 0ULL;
#pragma unroll
            for (int k = 0; k < T; ++k) a = fma2(dp[jh][k], pkv[k], a);
            hh[ch][jh] = a;
        }
    }

    // per-o-pair mixing (v2.u64 alpha loads) fused with vertical scatter
#pragma unroll
    for (int op = 0; op < OCG; op += 2) {
        ull m0[3] = {0ULL, 0ULL, 0ULL};
        ull m1[3] = {0ULL, 0ULL, 0ULL};
#pragma unroll
        for (int n = 0; n < NB; ++n) {
            const int iv = IV[n], jh = JH[n];
#pragma unroll
            for (int ch = 0; ch < ICG; ++ch) {
                ulonglong2 a2 = *(const ulonglong2*)&sA[n][ch][op];
                ull t = hh[ch][jh];
                m0[iv] = fma2(a2.x, t, m0[iv]);
                m1[iv] = fma2(a2.y, t, m1[iv]);
            }
        }
#pragma unroll
        for (int k = 0; k < T; ++k) {
            if (HEAD && k > i) continue;
            const int s = ((u - k + 2 * F) % T + T) % T;
            ull a0 = acc[s][op];
            a0 = fma2(dp[0][k], m0[0], a0);
            a0 = fma2(dp[1][k], m0[1], a0);
            a0 = fma2(dp[2][k], m0[2], a0);
            acc[s][op] = a0;
            ull a1 = acc[s][op + 1];
            a1 = fma2(dp[0][k], m1[0], a1);
            a1 = fma2(dp[1][k], m1[1], a1);
            a1 = fma2(dp[2][k], m1[2], a1);
            acc[s][op + 1] = a1;
        }
    }

    // store completed row (ring slot u)
    if (i >= 2 * F && i < SH + 2 * F) {
        int y = y0 + i - 2 * F;
#pragma unroll
        for (int o = 0; o < OCG; ++o) {
            float lo, hi;
            unpk2(acc[u][o], lo, hi);
            *(float2*)(outb + ((size_t)o * H + y) * W + x0) = make_float2(lo, hi);
            acc[u][o] = 0ULL;
        }
    }
}

// ---- conv body -------------------------------------------------------------
template <int T>
__device__ __forceinline__ void srf_conv_body(
    const float* __restrict__ inb, float* __restrict__ outb, int g,
    int x0, int y0, const float2 (*__restrict__ sA)[ICG][OCG]) {
    constexpr int F = T / 2;
    constexpr int ITER = ((SH + 2 * F + T - 1) / T) * T;

    ull dp[3][T];
#pragma unroll
    for (int d = 0; d < 3; ++d)
#pragma unroll
        for (int k = 0; k < T; ++k)
            dp[d][k] = *(const ull*)&g_dp[g][d][k];

    bool xv[T + 1];
#pragma unroll
    for (int j = 0; j <= T; ++j) {
        int xx = x0 - F + j;
        xv[j] = (xx >= 0 && xx < W);
    }

    ull acc[T][OCG];
#pragma unroll
    for (int s = 0; s < T; ++s)
#pragma unroll
        for (int o = 0; o < OCG; ++o) acc[s][o] = 0ULL;

    // peeled head block (ghost-term guard k<=i)
#pragma unroll
    for (int u = 0; u < T; ++u)
        srf_row_step<T, true>(u, u, y0, x0, xv, inb, outb, dp, sA, acc);

    for (int ib = T; ib < ITER; ib += T) {
#pragma unroll
        for (int u = 0; u < T; ++u)
            srf_row_step<T, false>(ib + u, u, y0, x0, xv, inb, outb, dp, sA, acc);
    }
}

// ---- combined conv kernel --------------------------------------------------
// grid: (3, H/SH, B*NG), 64 threads = 64 column pairs (128 columns).
__global__ void __launch_bounds__(64, 5)
srf_conv_all(const float* __restrict__ in, float* __restrict__ out) {
    int g = blockIdx.z % NG;
    int b = blockIdx.z / NG;

    int x0 = 2 * (blockIdx.x * 64 + threadIdx.x);
    int y0 = blockIdx.y * SH;

    const float* inb = in + ((size_t)b * INC + (size_t)g * ICG) * (H * W);
    float* outb      = out + ((size_t)b * OUTC + (size_t)g * OCG) * (H * W);

    __shared__ __align__(16) float2 sA[NB][ICG][OCG];
    {
        const float2* src = (const float2*)g_alpha[g];
        for (int idx = threadIdx.x; idx < NB * ICG * OCG; idx += 64)
            ((float2*)sA)[idx] = src[idx];
    }
    __syncthreads();

    if (g < 3)
        srf_conv_body<3>(inb, outb, g, x0, y0, sA);
    else
        srf_conv_body<5>(inb, outb, g, x0, y0, sA);
}

extern "C" void kernel_launch(void* const* d_in, const int* in_sizes, int n_in,
                              void* d_out, int out_size) {
    const float* data   = (const float*)d_in[0];
    const float* alphas = (const float*)d_in[1];
    const float* scales = (const float*)d_in[2];
    float* out = (float*)d_out;

    srf_precompute<<<1, 256>>>(alphas, scales);

    dim3 blk(64, 1, 1);
    dim3 grid(3, H / SH, B * NG);
    srf_conv_all<<<grid, blk>>>(data, out);
}

// round 4
// speedup vs baseline: 1.4178x; 1.4178x over previous
#include <cuda_runtime.h>
#include <cuda_bf16.h>

// ---------------------------------------------------------------------------
// SRF layer: grouped conv, filters = Gaussian-Hermite (order 2) bases mixed by
// learned alphas. 5 groups, 4 in-ch -> 8 out-ch per group. Separable basis.
//   precompute: sigma -> taps (lane-duplicated f32x2) + duplicated alphas.
//   conv: one kernel, runtime tap-count dispatch (3 vs 5) per group.
//     per-thread column pair: horizontal conv -> per-o-pair mixing ->
//     vertical scatter into T-deep accumulator ring, packed f32x2 throughout.
//   Head rows guard scatter (k<=i); final partial block peeled (u<LAST).
//   SH=32 -> 2880 blocks so ~39 warps/SM co-resident (latency hiding).
// ---------------------------------------------------------------------------

#define H 384
#define W 384
#define B 16
#define INC 20
#define OUTC 40
#define NG 5
#define ICG 4
#define OCG 8
#define NB 6
#define SH 32          // strip height (384/32 = 12 strips)

__device__ float2 g_dp[NG][3][5];
__device__ float2 g_alpha[NG][NB][ICG][OCG];

typedef unsigned long long ull;

__device__ __forceinline__ ull pk2(float a, float b) {
    ull r; asm("mov.b64 %0, {%1, %2};" : "=l"(r) : "f"(a), "f"(b)); return r;
}
__device__ __forceinline__ ull fma2(ull a, ull b, ull c) {
    ull d; asm("fma.rn.f32x2 %0, %1, %2, %3;" : "=l"(d) : "l"(a), "l"(b), "l"(c));
    return d;
}
__device__ __forceinline__ void unpk2(ull v, float& lo, float& hi) {
    asm("mov.b64 {%0, %1}, %2;" : "=f"(lo), "=f"(hi) : "l"(v));
}

// ---- precompute ------------------------------------------------------------
__global__ void srf_precompute(const float* __restrict__ alphas,
                               const float* __restrict__ scales) {
    int tid = threadIdx.x;
    if (tid < NG) {
        const int FSarr[5] = {1, 1, 1, 2, 2};
        int s = tid;
        float mn = 0.2f * s, mx = mn + 0.2f;
        float sigma = (mx - mn) * 0.5f * tanhf(scales[s]) + (mn + mx) * 0.5f;
        int F = FSarr[s];
        int T = 2 * F + 1;
        float g[5];
        float sum = 0.f;
        for (int k = 0; k < T; ++k) {
            float x = (float)(k - F);
            g[k] = expf(-(x * x) / (2.f * sigma * sigma));
            sum += g[k];
        }
        float inv = 1.f / sum;
        float c1 = -1.f / (sigma * 1.41421356237309515f);
        for (int k = 0; k < 5; ++k) {
            float d0 = 0.f, d1 = 0.f, d2 = 0.f;
            if (k < T) {
                float x = (float)(k - F);
                float gg = g[k] * inv;
                float u = x / (sigma * 1.41421356237309515f);
                d0 = gg;
                d1 = c1 * (2.f * u) * gg;
                d2 = (c1 * c1) * (4.f * u * u - 2.f) * gg;
            }
            g_dp[s][0][k] = make_float2(d0, d0);
            g_dp[s][1][k] = make_float2(d1, d1);
            g_dp[s][2][k] = make_float2(d2, d2);
        }
    }
    for (int idx = tid; idx < NG * NB * ICG * OCG; idx += blockDim.x) {
        float a = alphas[idx];
        ((float2*)g_alpha)[idx] = make_float2(a, a);
    }
}

// ---- one row step ----------------------------------------------------------
template <int T, bool HEAD>
__device__ __forceinline__ void srf_row_step(
    int i, int u, int y0, int x0,
    const bool (&xv)[T + 1],
    const float* __restrict__ inb, float* __restrict__ outb,
    const ull (&dp)[3][T],
    const float2 (*__restrict__ sA)[ICG][OCG],
    ull (&acc)[T][OCG]) {
    constexpr int F = T / 2;
    const int IV[NB] = {0, 0, 0, 1, 1, 2};
    const int JH[NB] = {0, 1, 2, 0, 1, 0};

    int r = y0 - F + i;
    bool rv = (r >= 0 && r < H);

    // horizontal pass
    ull hh[ICG][3];
#pragma unroll
    for (int ch = 0; ch < ICG; ++ch) {
        const float* row = inb + ((size_t)ch * H + (size_t)(rv ? r : 0)) * W;
        float w[T + 1];
#pragma unroll
        for (int j = 0; j <= T; ++j) {
            int xx = x0 - F + j;
            w[j] = (rv && xv[j]) ? __ldg(row + xx) : 0.f;
        }
        ull pkv[T];
#pragma unroll
        for (int k = 0; k < T; ++k) pkv[k] = pk2(w[k], w[k + 1]);
#pragma unroll
        for (int jh = 0; jh < 3; ++jh) {
            ull a = 0ULL;
#pragma unroll
            for (int k = 0; k < T; ++k) a = fma2(dp[jh][k], pkv[k], a);
            hh[ch][jh] = a;
        }
    }

    // per-o-pair mixing fused with vertical scatter
#pragma unroll
    for (int op = 0; op < OCG; op += 2) {
        ull m0[3] = {0ULL, 0ULL, 0ULL};
        ull m1[3] = {0ULL, 0ULL, 0ULL};
#pragma unroll
        for (int n = 0; n < NB; ++n) {
            const int iv = IV[n], jh = JH[n];
#pragma unroll
            for (int ch = 0; ch < ICG; ++ch) {
                ulonglong2 a2 = *(const ulonglong2*)&sA[n][ch][op];
                ull t = hh[ch][jh];
                m0[iv] = fma2(a2.x, t, m0[iv]);
                m1[iv] = fma2(a2.y, t, m1[iv]);
            }
        }
#pragma unroll
        for (int k = 0; k < T; ++k) {
            if (HEAD && k > i) continue;
            const int s = ((u - k + 2 * F) % T + T) % T;
            ull a0 = acc[s][op];
            a0 = fma2(dp[0][k], m0[0], a0);
            a0 = fma2(dp[1][k], m0[1], a0);
            a0 = fma2(dp[2][k], m0[2], a0);
            acc[s][op] = a0;
            ull a1 = acc[s][op + 1];
            a1 = fma2(dp[0][k], m1[0], a1);
            a1 = fma2(dp[1][k], m1[1], a1);
            a1 = fma2(dp[2][k], m1[2], a1);
            acc[s][op + 1] = a1;
        }
    }

    // store completed row (ring slot u)
    if (i >= 2 * F && i < SH + 2 * F) {
        int y = y0 + i - 2 * F;
#pragma unroll
        for (int o = 0; o < OCG; ++o) {
            float lo, hi;
            unpk2(acc[u][o], lo, hi);
            *(float2*)(outb + ((size_t)o * H + y) * W + x0) = make_float2(lo, hi);
            acc[u][o] = 0ULL;
        }
    }
}

// ---- conv body -------------------------------------------------------------
template <int T>
__device__ __forceinline__ void srf_conv_body(
    const float* __restrict__ inb, float* __restrict__ outb, int g,
    int x0, int y0, const float2 (*__restrict__ sA)[ICG][OCG]) {
    constexpr int F = T / 2;
    constexpr int ROWS = SH + 2 * F;                 // valid row-steps
    constexpr int ITER = ((ROWS + T - 1) / T) * T;   // padded to T
    constexpr int LAST = ROWS - (ITER - T);          // rows in final block

    ull dp[3][T];
#pragma unroll
    for (int d = 0; d < 3; ++d)
#pragma unroll
        for (int k = 0; k < T; ++k)
            dp[d][k] = *(const ull*)&g_dp[g][d][k];

    bool xv[T + 1];
#pragma unroll
    for (int j = 0; j <= T; ++j) {
        int xx = x0 - F + j;
        xv[j] = (xx >= 0 && xx < W);
    }

    ull acc[T][OCG];
#pragma unroll
    for (int s = 0; s < T; ++s)
#pragma unroll
        for (int o = 0; o < OCG; ++o) acc[s][o] = 0ULL;

    // peeled head block (ghost-term guard k<=i)
#pragma unroll
    for (int u = 0; u < T; ++u)
        srf_row_step<T, true>(u, u, y0, x0, xv, inb, outb, dp, sA, acc);

    // full steady blocks
    for (int ib = T; ib < ITER - T; ib += T) {
#pragma unroll
        for (int u = 0; u < T; ++u)
            srf_row_step<T, false>(ib + u, u, y0, x0, xv, inb, outb, dp, sA, acc);
    }

    // final (possibly partial) block — skip dead rows at compile time
    {
        const int ib = ITER - T;
#pragma unroll
        for (int u = 0; u < T; ++u) {
            if (u >= LAST) break;
            srf_row_step<T, false>(ib + u, u, y0, x0, xv, inb, outb, dp, sA, acc);
        }
    }
}

// ---- combined conv kernel --------------------------------------------------
// grid: (3, H/SH, B*NG), 64 threads = 64 column pairs (128 columns).
__global__ void __launch_bounds__(64)
srf_conv_all(const float* __restrict__ in, float* __restrict__ out) {
    int g = blockIdx.z % NG;
    int b = blockIdx.z / NG;

    int x0 = 2 * (blockIdx.x * 64 + threadIdx.x);
    int y0 = blockIdx.y * SH;

    const float* inb = in + ((size_t)b * INC + (size_t)g * ICG) * (H * W);
    float* outb      = out + ((size_t)b * OUTC + (size_t)g * OCG) * (H * W);

    __shared__ __align__(16) float2 sA[NB][ICG][OCG];
    {
        const float2* src = (const float2*)g_alpha[g];
        for (int idx = threadIdx.x; idx < NB * ICG * OCG; idx += 64)
            ((float2*)sA)[idx] = src[idx];
    }
    __syncthreads();

    if (g < 3)
        srf_conv_body<3>(inb, outb, g, x0, y0, sA);
    else
        srf_conv_body<5>(inb, outb, g, x0, y0, sA);
}

extern "C" void kernel_launch(void* const* d_in, const int* in_sizes, int n_in,
                              void* d_out, int out_size) {
    const float* data   = (const float*)d_in[0];
    const float* alphas = (const float*)d_in[1];
    const float* scales = (const float*)d_in[2];
    float* out = (float*)d_out;

    srf_precompute<<<1, 256>>>(alphas, scales);

    dim3 blk(64, 1, 1);
    dim3 grid(3, H / SH, B * NG);
    srf_conv_all<<<grid, blk>>>(data, out);
}